// round 1
// baseline (speedup 1.0000x reference)
#include <cuda_runtime.h>
#include <cstdint>
#include <cstddef>

// Farthest Point Sampling: B=8, N=131072, NPOINT=1024, output [8,1024,3] fp32.
//
// One persistent cluster-cooperative kernel:
//   grid = 64 CTAs, cluster (8,1,1)  -> 8 clusters, one per batch
//   each CTA: 16384 points in SMEM (SoA), mindist in registers (32/thread)
//   per step: register update + packed-u64 argmax, DSMEM all-to-all partial
//   exchange (double-buffered), single barrier.cluster per step.

#define NB      8
#define NPTS    131072
#define NSAMP   1024
#define CSIZE   8
#define TPB     512
#define PPB     (NPTS / CSIZE)   // 16384 points per CTA
#define PPT     (PPB / TPB)      // 32 points per thread
#define NWARPS  (TPB / 32)       // 16

struct Smem {
    unsigned long long slots[2][CSIZE];   // double-buffered cross-CTA partials
    unsigned long long warpred[NWARPS];   // intra-block warp partials
    float cent[4];                        // current centroid broadcast
    float xs[PPB];
    float ys[PPB];
    float zs[PPB];
};

__device__ __forceinline__ unsigned ctarank() {
    unsigned r;
    asm("mov.u32 %0, %%cluster_ctarank;" : "=r"(r));
    return r;
}

__device__ __forceinline__ unsigned long long u64max(unsigned long long a,
                                                     unsigned long long b) {
    return a > b ? a : b;
}

__global__ void __launch_bounds__(TPB, 1)
fps_kernel(const float* __restrict__ xyz, float* __restrict__ out) {
    extern __shared__ __align__(16) unsigned char smem_raw[];
    Smem* s = reinterpret_cast<Smem*>(smem_raw);

    const int      tid   = threadIdx.x;
    const unsigned lane  = tid & 31;
    const unsigned warp  = (unsigned)tid >> 5;
    const unsigned rank  = ctarank();
    const int      batch = blockIdx.x / CSIZE;

    const float* __restrict__ base = xyz + (size_t)batch * NPTS * 3;
    const unsigned pbase = rank * PPB;

    // ---- load this CTA's 16384 points into SMEM (SoA) ----
    for (int i = tid; i < PPB; i += TPB) {
        const float* p = base + (size_t)(pbase + (unsigned)i) * 3;
        s->xs[i] = p[0];
        s->ys[i] = p[1];
        s->zs[i] = p[2];
    }

    // mindist lives in registers
    float m[PPT];
#pragma unroll
    for (int k = 0; k < PPT; ++k) m[k] = __int_as_float(0x7f800000);  // +inf

    // ---- initial centroid = point 0; emit sample 0 ----
    if (tid == 0) {
        float cx = base[0], cy = base[1], cz = base[2];
        s->cent[0] = cx; s->cent[1] = cy; s->cent[2] = cz;
        if (rank == 0) {
            float* o = out + (size_t)batch * NSAMP * 3;
            o[0] = cx; o[1] = cy; o[2] = cz;
        }
    }
    __syncthreads();

    for (int t = 1; t < NSAMP; ++t) {
        const float cx = s->cent[0];
        const float cy = s->cent[1];
        const float cz = s->cent[2];

        // ---- update mindist, track packed argmax key ----
        // key = (bits(mindist) << 32) | ~global_idx :
        //   u64 max == (largest dist, ties -> smallest index)
        unsigned long long key = 0ULL;
#pragma unroll
        for (int k = 0; k < PPT; ++k) {
            const int i = k * TPB + tid;                 // conflict-free LDS
            float dx = s->xs[i] - cx;
            float dy = s->ys[i] - cy;
            float dz = s->zs[i] - cz;
            float d  = dx * dx + dy * dy + dz * dz;
            float mm = fminf(m[k], d);
            m[k] = mm;
            unsigned long long kk =
                ((unsigned long long)__float_as_uint(mm) << 32) |
                (unsigned)~(pbase + (unsigned)i);
            key = u64max(key, kk);
        }

        // ---- warp reduce ----
#pragma unroll
        for (int off = 16; off > 0; off >>= 1)
            key = u64max(key, __shfl_down_sync(0xffffffffu, key, off));
        if (lane == 0) s->warpred[warp] = key;
        __syncthreads();

        // ---- block reduce (warp 0) + push partial to all 8 peer CTAs ----
        if (warp == 0) {
            key = (lane < NWARPS) ? s->warpred[lane] : 0ULL;
#pragma unroll
            for (int off = 8; off > 0; off >>= 1)
                key = u64max(key, __shfl_down_sync(0xffffffffu, key, off));
            key = __shfl_sync(0xffffffffu, key, 0);

            if (lane < CSIZE) {
                // write my block partial into slots[t&1][rank] of CTA `lane`
                unsigned long long* lslot = &s->slots[t & 1][rank];
                unsigned laddr = (unsigned)__cvta_generic_to_shared(lslot);
                unsigned raddr;
                asm volatile("mapa.shared::cluster.u32 %0, %1, %2;"
                             : "=r"(raddr) : "r"(laddr), "r"(lane));
                asm volatile("st.shared::cluster.u64 [%0], %1;"
                             :: "r"(raddr), "l"(key) : "memory");
            }
        }

        // one cluster barrier per step (release/acquire orders the DSMEM stores)
        asm volatile("barrier.cluster.arrive.aligned;" ::: "memory");
        asm volatile("barrier.cluster.wait.aligned;"   ::: "memory");

        // ---- every CTA reduces the 8 slots locally; fetch next centroid ----
        if (warp == 0) {
            unsigned long long kk = (lane < CSIZE) ? s->slots[t & 1][lane] : 0ULL;
#pragma unroll
            for (int off = 4; off > 0; off >>= 1)
                kk = u64max(kk, __shfl_down_sync(0xffffffffu, kk, off));
            if (lane == 0) {
                unsigned g = ~(unsigned)kk;            // winning global index
                const float* p = base + (size_t)g * 3; // L2-resident
                float nx = __ldg(p + 0);
                float ny = __ldg(p + 1);
                float nz = __ldg(p + 2);
                s->cent[0] = nx; s->cent[1] = ny; s->cent[2] = nz;
                if (rank == 0) {
                    float* o = out + ((size_t)batch * NSAMP + (size_t)t) * 3;
                    o[0] = nx; o[1] = ny; o[2] = nz;
                }
            }
        }
        __syncthreads();
    }

    // keep all CTAs alive until the last DSMEM traffic is done
    asm volatile("barrier.cluster.arrive.aligned;" ::: "memory");
    asm volatile("barrier.cluster.wait.aligned;"   ::: "memory");
}

extern "C" void kernel_launch(void* const* d_in, const int* in_sizes, int n_in,
                              void* d_out, int out_size) {
    (void)in_sizes; (void)n_in; (void)out_size;
    const float* xyz = (const float*)d_in[0];
    float* out = (float*)d_out;

    cudaFuncSetAttribute(fps_kernel,
                         cudaFuncAttributeMaxDynamicSharedMemorySize,
                         (int)sizeof(Smem));

    cudaLaunchConfig_t cfg = {};
    cfg.gridDim  = dim3(NB * CSIZE, 1, 1);
    cfg.blockDim = dim3(TPB, 1, 1);
    cfg.dynamicSmemBytes = sizeof(Smem);
    cfg.stream = 0;

    cudaLaunchAttribute attr[1];
    attr[0].id = cudaLaunchAttributeClusterDimension;
    attr[0].val.clusterDim.x = CSIZE;
    attr[0].val.clusterDim.y = 1;
    attr[0].val.clusterDim.z = 1;
    cfg.attrs = attr;
    cfg.numAttrs = 1;

    cudaLaunchKernelEx(&cfg, fps_kernel, xyz, out);
}